// round 4
// baseline (speedup 1.0000x reference)
#include <cuda_runtime.h>

#define F   16
#define HID 64
#define NN  100000
#define EE  3200000
#define ROUNDS 5

typedef unsigned long long ull;

__device__ __align__(256) float g_edges[(size_t)F * EE];   // [F][E]
__device__ __align__(256) float g_nodes[F * NN];           // [F][N]
__device__ __align__(256) float g_sent[NN * F];            // [N][F]
__device__ __align__(256) float g_recv[NN * F];            // [N][F]
__device__ __align__(256) float g_ps[NN * HID];            // [N][HID]  eW1_s @ nodes + eb1
__device__ __align__(256) float g_pr[NN * HID];            // [N][HID]  eW1_r @ nodes

__device__ __forceinline__ ull pack2(float a, float b) {
    ull r; asm("mov.b64 %0, {%1,%2};" : "=l"(r) : "f"(a), "f"(b)); return r;
}
__device__ __forceinline__ void unpack2(ull v, float& a, float& b) {
    asm("mov.b64 {%0,%1}, %2;" : "=f"(a), "=f"(b) : "l"(v));
}
__device__ __forceinline__ ull fma2(ull a, ull b, ull c) {
    ull d; asm("fma.rn.f32x2 %0, %1, %2, %3;" : "=l"(d) : "l"(a), "l"(b), "l"(c)); return d;
}
__device__ __forceinline__ ull add2(ull a, ull b) {
    ull d; asm("add.rn.f32x2 %0, %1, %2;" : "=l"(d) : "l"(a), "l"(b)); return d;
}

__global__ void zero_agg_kernel() {
    int i = blockIdx.x * blockDim.x + threadIdx.x;
    const int n4 = (NN * F) / 4;
    float4 z = make_float4(0.f, 0.f, 0.f, 0.f);
    if (i < n4) {
        reinterpret_cast<float4*>(g_sent)[i] = z;
        reinterpret_cast<float4*>(g_recv)[i] = z;
    }
}

__global__ void scatter_kernel(const float* __restrict__ edges,
                               const int* __restrict__ snd, const int* __restrict__ rcv) {
    int e = blockIdx.x * blockDim.x + threadIdx.x;
    if (e >= EE) return;
    int s = snd[e];
    int r = rcv[e];
    float v[F];
#pragma unroll
    for (int f = 0; f < F; f++) v[f] = __ldcs(&edges[(size_t)f * EE + e]);
    float* ps = &g_sent[(size_t)s * F];
    float* pr = &g_recv[(size_t)r * F];
#pragma unroll
    for (int f = 0; f < F; f += 4) {
        asm volatile("red.global.add.v4.f32 [%0], {%1,%2,%3,%4};"
                     :: "l"(ps + f), "f"(v[f]), "f"(v[f + 1]), "f"(v[f + 2]), "f"(v[f + 3])
                     : "memory");
        asm volatile("red.global.add.v4.f32 [%0], {%1,%2,%3,%4};"
                     :: "l"(pr + f), "f"(v[f]), "f"(v[f + 1]), "f"(v[f + 2]), "f"(v[f + 3])
                     : "memory");
    }
}

// fused node MLP + edge projections (unchanged from R3; verified correct)
__global__ void __launch_bounds__(256)
node_proj_kernel(const float* src_nodes_in, float* out_nodes,
                 const float* __restrict__ W1, const float* __restrict__ b1,
                 const float* __restrict__ W2, const float* __restrict__ b2,
                 const float* __restrict__ eW1, const float* __restrict__ eb1) {
    const float* __restrict__ src_nodes = src_nodes_in ? src_nodes_in : g_nodes;
    __shared__ __align__(16) float s_w1t[48 * HID];
    __shared__ __align__(16) float s_w2t[HID * F];
    __shared__ __align__(16) float s_ws[16 * HID];
    __shared__ __align__(16) float s_wr[16 * HID];
    __shared__ __align__(16) float s_b1[HID];
    __shared__ __align__(16) float s_b2[F];
    __shared__ __align__(16) float s_eb1[HID];
    for (int i = threadIdx.x; i < 48 * HID; i += blockDim.x) {
        int k = i >> 6, h = i & 63;
        s_w1t[i] = W1[h * 48 + k];
    }
    for (int i = threadIdx.x; i < HID * F; i += blockDim.x) {
        int h = i >> 4, o = i & 15;
        s_w2t[i] = W2[o * HID + h];
    }
    for (int i = threadIdx.x; i < 16 * HID; i += blockDim.x) {
        int k = i >> 6, h = i & 63;
        s_ws[i] = eW1[h * 48 + 16 + k];
        s_wr[i] = eW1[h * 48 + 32 + k];
    }
    if (threadIdx.x < HID) { s_b1[threadIdx.x] = b1[threadIdx.x]; s_eb1[threadIdx.x] = eb1[threadIdx.x]; }
    if (threadIdx.x < F)   s_b2[threadIdx.x] = b2[threadIdx.x];
    __syncthreads();

    int n = blockIdx.x * blockDim.x + threadIdx.x;
    if (n >= NN) return;

    ull acc[HID / 2];
#pragma unroll
    for (int j = 0; j < HID / 4; j++) {
        ulonglong2 bv = *reinterpret_cast<const ulonglong2*>(&s_b1[j * 4]);
        acc[2 * j] = bv.x; acc[2 * j + 1] = bv.y;
    }
#pragma unroll
    for (int k = 0; k < 16; k++) {
        float xk = src_nodes[(size_t)k * NN + n];
        ull xs = pack2(xk, xk);
        const ulonglong2* w = reinterpret_cast<const ulonglong2*>(&s_w1t[k * HID]);
#pragma unroll
        for (int m = 0; m < 16; m++) {
            ulonglong2 wv = w[m];
            acc[2 * m]     = fma2(wv.x, xs, acc[2 * m]);
            acc[2 * m + 1] = fma2(wv.y, xs, acc[2 * m + 1]);
        }
    }
#pragma unroll
    for (int seg = 0; seg < 2; seg++) {
        const float* aggr = seg == 0 ? &g_sent[(size_t)n * F] : &g_recv[(size_t)n * F];
        float xv[16];
#pragma unroll
        for (int q = 0; q < 4; q++) {
            float4 v = *reinterpret_cast<const float4*>(&aggr[q * 4]);
            xv[q * 4] = v.x; xv[q * 4 + 1] = v.y; xv[q * 4 + 2] = v.z; xv[q * 4 + 3] = v.w;
        }
#pragma unroll
        for (int k = 0; k < 16; k++) {
            ull xs = pack2(xv[k], xv[k]);
            const ulonglong2* w = reinterpret_cast<const ulonglong2*>(&s_w1t[((seg + 1) * 16 + k) * HID]);
#pragma unroll
            for (int m = 0; m < 16; m++) {
                ulonglong2 wv = w[m];
                acc[2 * m]     = fma2(wv.x, xs, acc[2 * m]);
                acc[2 * m + 1] = fma2(wv.y, xs, acc[2 * m + 1]);
            }
        }
    }

    ull o[F / 2];
#pragma unroll
    for (int j = 0; j < 4; j++) {
        ulonglong2 bv = *reinterpret_cast<const ulonglong2*>(&s_b2[j * 4]);
        o[2 * j] = bv.x; o[2 * j + 1] = bv.y;
    }
#pragma unroll
    for (int h = 0; h < HID; h += 2) {
        float h0, h1; unpack2(acc[h >> 1], h0, h1);
        h0 = fmaxf(h0, 0.f); h1 = fmaxf(h1, 0.f);
        ull x0 = pack2(h0, h0), x1 = pack2(h1, h1);
        const ulonglong2* w0 = reinterpret_cast<const ulonglong2*>(&s_w2t[h * F]);
        const ulonglong2* w1 = reinterpret_cast<const ulonglong2*>(&s_w2t[(h + 1) * F]);
#pragma unroll
        for (int m = 0; m < 4; m++) {
            ulonglong2 a = w0[m], b = w1[m];
            o[2 * m]     = fma2(a.x, x0, o[2 * m]);
            o[2 * m]     = fma2(b.x, x1, o[2 * m]);
            o[2 * m + 1] = fma2(a.y, x0, o[2 * m + 1]);
            o[2 * m + 1] = fma2(b.y, x1, o[2 * m + 1]);
        }
    }
    float y[F];
#pragma unroll
    for (int j = 0; j < F / 2; j++) unpack2(o[j], y[2 * j], y[2 * j + 1]);
#pragma unroll
    for (int k = 0; k < F; k++) {
        g_nodes[(size_t)k * NN + n] = y[k];
    }
    if (out_nodes) {
#pragma unroll
        for (int k = 0; k < F; k++) out_nodes[(size_t)k * NN + n] = y[k];
    }

#pragma unroll
    for (int j = 0; j < HID / 4; j++) {
        ulonglong2 bv = *reinterpret_cast<const ulonglong2*>(&s_eb1[j * 4]);
        acc[2 * j] = bv.x; acc[2 * j + 1] = bv.y;
    }
#pragma unroll
    for (int k = 0; k < 16; k++) {
        ull xs = pack2(y[k], y[k]);
        const ulonglong2* w = reinterpret_cast<const ulonglong2*>(&s_ws[k * HID]);
#pragma unroll
        for (int m = 0; m < 16; m++) {
            ulonglong2 wv = w[m];
            acc[2 * m]     = fma2(wv.x, xs, acc[2 * m]);
            acc[2 * m + 1] = fma2(wv.y, xs, acc[2 * m + 1]);
        }
    }
    ull* outp = reinterpret_cast<ull*>(&g_ps[(size_t)n * HID]);
#pragma unroll
    for (int j = 0; j < HID / 2; j++) outp[j] = acc[j];

#pragma unroll
    for (int j = 0; j < HID / 2; j++) acc[j] = 0ull;
#pragma unroll
    for (int k = 0; k < 16; k++) {
        ull xs = pack2(y[k], y[k]);
        const ulonglong2* w = reinterpret_cast<const ulonglong2*>(&s_wr[k * HID]);
#pragma unroll
        for (int m = 0; m < 16; m++) {
            ulonglong2 wv = w[m];
            acc[2 * m]     = fma2(wv.x, xs, acc[2 * m]);
            acc[2 * m + 1] = fma2(wv.y, xs, acc[2 * m + 1]);
        }
    }
    outp = reinterpret_cast<ull*>(&g_pr[(size_t)n * HID]);
#pragma unroll
    for (int j = 0; j < HID / 2; j++) outp[j] = acc[j];
}

// ---------------- edge MLP v3: 2 threads per edge (hidden-dim split) ---------
#define ETPB 256
#define EPB  128                         // edges per block
#define SG_STRIDE 68
#define EDGE_SMEM_FLOATS (EPB * SG_STRIDE + 16 * 64 + 64 * 16 + 16)

__global__ void __launch_bounds__(ETPB, 3)
edge_mlp_kernel(const float* src_edges_in, float* dst_edges_in,
                const int* __restrict__ snd, const int* __restrict__ rcv,
                const float* __restrict__ eW1, const float* __restrict__ eW2,
                const float* __restrict__ eb2, int do_scatter) {
    const float* __restrict__ src_edges = src_edges_in ? src_edges_in : g_edges;
    float* __restrict__ dst_edges = dst_edges_in ? dst_edges_in : g_edges;
    extern __shared__ __align__(16) float smem[];
    float* s_g   = smem;                         // EPB x 68
    float* s_w1t = smem + EPB * SG_STRIDE;       // [k][h]  16x64
    float* s_w2t = s_w1t + 16 * 64;              // [h][o]  64x16
    float* s_b2  = s_w2t + 64 * 16;              // 16

    const int tid = threadIdx.x;
    for (int i = tid; i < 16 * 64; i += ETPB) { int k = i >> 6, h = i & 63; s_w1t[i] = eW1[h * 48 + k]; }
    for (int i = tid; i < 64 * 16; i += ETPB) { int h = i >> 4, o = i & 15; s_w2t[i] = eW2[o * 64 + h]; }
    if (tid < 16) s_b2[tid] = eb2[tid];

    const int e0 = blockIdx.x * EPB;

    // ---- cooperative gather staging: s_g[el][:] = g_ps[s_el][:] + g_pr[r_el][:]
    {
        const int wid  = tid >> 5;        // 8 warps, 16 rows each
        const int lane = tid & 31;
        const int sub  = lane >> 4;       // 2 rows per iteration
        const int c    = lane & 15;       // 16B chunk within 256B row
#pragma unroll
        for (int i = 0; i < 16; i += 2) {
            int el = wid * 16 + i + sub;
            int s = snd[e0 + el];
            int r = rcv[e0 + el];
            ulonglong2 a = *reinterpret_cast<const ulonglong2*>(&g_ps[(size_t)s * HID + c * 4]);
            ulonglong2 b = *reinterpret_cast<const ulonglong2*>(&g_pr[(size_t)r * HID + c * 4]);
            ulonglong2 v; v.x = add2(a.x, b.x); v.y = add2(a.y, b.y);
            *reinterpret_cast<ulonglong2*>(&s_g[el * SG_STRIDE + c * 4]) = v;
        }
    }
    __syncthreads();

    const int el   = tid >> 1;            // edge within block
    const int half = tid & 1;             // hidden-dim half: h in [32*half, 32*half+32)
    const size_t e = (size_t)e0 + el;

    // ---- layer-1 accumulators for this half (eb1 folded into g_ps)
    ull acc[16];                           // 32 h-values
    {
        const ulonglong2* grow = reinterpret_cast<const ulonglong2*>(&s_g[el * SG_STRIDE + half * 32]);
#pragma unroll
        for (int m = 0; m < 8; m++) {
            ulonglong2 v = grow[m];
            acc[2 * m] = v.x; acc[2 * m + 1] = v.y;
        }
    }

    // ---- layer 1: += eW1_e @ edge (this half's 32 rows)
#pragma unroll
    for (int k = 0; k < 16; k++) {
        float x = __ldcs(&src_edges[(size_t)k * EE + e]);
        ull xs = pack2(x, x);
        const ulonglong2* w = reinterpret_cast<const ulonglong2*>(&s_w1t[k * HID + half * 32]);
#pragma unroll
        for (int m = 0; m < 8; m++) {
            ulonglong2 wv = w[m];
            acc[2 * m]     = fma2(wv.x, xs, acc[2 * m]);
            acc[2 * m + 1] = fma2(wv.y, xs, acc[2 * m + 1]);
        }
    }

    // ---- layer 2 partial: relu over this half's 32 h -> partial 16 outputs
    ull o[8];
    if (half == 0) {
#pragma unroll
        for (int j = 0; j < 4; j++) {
            ulonglong2 bv = *reinterpret_cast<const ulonglong2*>(&s_b2[j * 4]);
            o[2 * j] = bv.x; o[2 * j + 1] = bv.y;
        }
    } else {
#pragma unroll
        for (int j = 0; j < 8; j++) o[j] = 0ull;
    }
#pragma unroll
    for (int hh = 0; hh < 32; hh += 2) {
        float h0, h1; unpack2(acc[hh >> 1], h0, h1);
        h0 = fmaxf(h0, 0.f); h1 = fmaxf(h1, 0.f);
        ull x0 = pack2(h0, h0), x1 = pack2(h1, h1);
        const int hg = half * 32 + hh;
        const ulonglong2* w0 = reinterpret_cast<const ulonglong2*>(&s_w2t[hg * F]);
        const ulonglong2* w1 = reinterpret_cast<const ulonglong2*>(&s_w2t[(hg + 1) * F]);
#pragma unroll
        for (int m = 0; m < 4; m++) {
            ulonglong2 a = w0[m], b = w1[m];
            o[2 * m]     = fma2(a.x, x0, o[2 * m]);
            o[2 * m]     = fma2(b.x, x1, o[2 * m]);
            o[2 * m + 1] = fma2(a.y, x0, o[2 * m + 1]);
            o[2 * m + 1] = fma2(b.y, x1, o[2 * m + 1]);
        }
    }

    // ---- combine halves via xor-shuffle (partner = lane^1)
    float ov[F];
#pragma unroll
    for (int j = 0; j < 8; j++) {
        float a, b; unpack2(o[j], a, b);
        a += __shfl_xor_sync(0xFFFFFFFFu, a, 1);
        b += __shfl_xor_sync(0xFFFFFFFFu, b, 1);
        ov[2 * j] = a; ov[2 * j + 1] = b;
    }

    // ---- write new edge features: even lane f 0..7, odd lane f 8..15
#pragma unroll
    for (int q = 0; q < 8; q++) {
        int f = q + half * 8;
        __stcs(&dst_edges[(size_t)f * EE + e], ov[f]);
    }

    // ---- fused scatter: even lane -> sent[s], odd lane -> recv[r]
    if (do_scatter) {
        int idx = half ? rcv[e] : snd[e];
        float* p = half ? &g_recv[(size_t)idx * F] : &g_sent[(size_t)idx * F];
#pragma unroll
        for (int f = 0; f < F; f += 4) {
            asm volatile("red.global.add.v4.f32 [%0], {%1,%2,%3,%4};"
                         :: "l"(p + f), "f"(ov[f]), "f"(ov[f + 1]), "f"(ov[f + 2]), "f"(ov[f + 3])
                         : "memory");
        }
    }
}

extern "C" void kernel_launch(void* const* d_in, const int* in_sizes, int n_in,
                              void* d_out, int out_size) {
    const float* nodes     = (const float*)d_in[0];
    const float* edges     = (const float*)d_in[1];
    const int*   receivers = (const int*)  d_in[2];
    const int*   senders   = (const int*)  d_in[3];
    const float* nW1 = (const float*)d_in[4];
    const float* nb1 = (const float*)d_in[5];
    const float* nW2 = (const float*)d_in[6];
    const float* nb2 = (const float*)d_in[7];
    const float* eW1 = (const float*)d_in[8];
    const float* eb1 = (const float*)d_in[9];
    const float* eW2 = (const float*)d_in[10];
    const float* eb2 = (const float*)d_in[11];
    float* out_nodes = (float*)d_out;
    float* out_edges = (float*)d_out + (size_t)F * NN;

    const int EDGE_BLOCKS = EE / EPB;                  // 25000
    const int NODE_BLOCKS = (NN + 255) / 256;          // 391
    const int ZERO_BLOCKS = ((NN * F) / 4 + 255) / 256;
    const int EDGE_SMEM = EDGE_SMEM_FLOATS * 4;        // 43072 bytes

    static int configured = 0;
    if (!configured) {
        cudaFuncSetAttribute(edge_mlp_kernel, cudaFuncAttributeMaxDynamicSharedMemorySize, EDGE_SMEM);
        configured = 1;
    }

    zero_agg_kernel<<<ZERO_BLOCKS, 256>>>();
    scatter_kernel<<<(EE + 255) / 256, 256>>>(edges, senders, receivers);

    for (int round = 0; round < ROUNDS; round++) {
        node_proj_kernel<<<NODE_BLOCKS, 256>>>(
            (round == 0) ? nodes : (const float*)0,
            (round == ROUNDS - 1) ? out_nodes : (float*)0,
            nW1, nb1, nW2, nb2, eW1, eb1);
        int do_scatter = (round < ROUNDS - 1);
        if (do_scatter) zero_agg_kernel<<<ZERO_BLOCKS, 256>>>();
        edge_mlp_kernel<<<EDGE_BLOCKS, ETPB, EDGE_SMEM>>>(
            (round == 0) ? edges : (const float*)0,
            (round == ROUNDS - 1) ? out_edges : (float*)0,
            senders, receivers, eW1, eW2, eb2, do_scatter);
    }
}

// round 5
// speedup vs baseline: 1.4591x; 1.4591x over previous
#include <cuda_runtime.h>

#define F   16
#define HID 64
#define NN  100000
#define EE  3200000
#define ROUNDS 5

typedef unsigned long long ull;

__device__ __align__(256) float g_edges[(size_t)EE * F];   // [E][F] internal layout
__device__ __align__(256) float g_nodes[F * NN];           // [F][N]
__device__ __align__(256) float g_sent[NN * F];            // [N][F]
__device__ __align__(256) float g_recv[NN * F];            // [N][F]
__device__ __align__(256) float g_ps[NN * HID];            // [N][HID]  eW1_s @ nodes + eb1
__device__ __align__(256) float g_pr[NN * HID];            // [N][HID]  eW1_r @ nodes

__device__ __forceinline__ ull pack2(float a, float b) {
    ull r; asm("mov.b64 %0, {%1,%2};" : "=l"(r) : "f"(a), "f"(b)); return r;
}
__device__ __forceinline__ void unpack2(ull v, float& a, float& b) {
    asm("mov.b64 {%0,%1}, %2;" : "=f"(a), "=f"(b) : "l"(v));
}
__device__ __forceinline__ ull fma2(ull a, ull b, ull c) {
    ull d; asm("fma.rn.f32x2 %0, %1, %2, %3;" : "=l"(d) : "l"(a), "l"(b), "l"(c)); return d;
}
__device__ __forceinline__ ull add2(ull a, ull b) {
    ull d; asm("add.rn.f32x2 %0, %1, %2;" : "=l"(d) : "l"(a), "l"(b)); return d;
}

__global__ void zero_agg_kernel() {
    int i = blockIdx.x * blockDim.x + threadIdx.x;
    const int n4 = (NN * F) / 4;
    float4 z = make_float4(0.f, 0.f, 0.f, 0.f);
    if (i < n4) {
        reinterpret_cast<float4*>(g_sent)[i] = z;
        reinterpret_cast<float4*>(g_recv)[i] = z;
    }
}

// round-0 scatter: reads the ORIGINAL [F][E] input edges
__global__ void scatter_kernel(const float* __restrict__ edges,
                               const int* __restrict__ snd, const int* __restrict__ rcv) {
    int e = blockIdx.x * blockDim.x + threadIdx.x;
    if (e >= EE) return;
    int s = snd[e];
    int r = rcv[e];
    float v[F];
#pragma unroll
    for (int f = 0; f < F; f++) v[f] = __ldcs(&edges[(size_t)f * EE + e]);
    float* ps = &g_sent[(size_t)s * F];
    float* pr = &g_recv[(size_t)r * F];
#pragma unroll
    for (int f = 0; f < F; f += 4) {
        asm volatile("red.global.add.v4.f32 [%0], {%1,%2,%3,%4};"
                     :: "l"(ps + f), "f"(v[f]), "f"(v[f + 1]), "f"(v[f + 2]), "f"(v[f + 3])
                     : "memory");
        asm volatile("red.global.add.v4.f32 [%0], {%1,%2,%3,%4};"
                     :: "l"(pr + f), "f"(v[f]), "f"(v[f + 1]), "f"(v[f + 2]), "f"(v[f + 3])
                     : "memory");
    }
}

// fused node MLP + edge projections (verified-correct structure)
__global__ void __launch_bounds__(256)
node_proj_kernel(const float* src_nodes_in, float* out_nodes,
                 const float* __restrict__ W1, const float* __restrict__ b1,
                 const float* __restrict__ W2, const float* __restrict__ b2,
                 const float* __restrict__ eW1, const float* __restrict__ eb1) {
    const float* __restrict__ src_nodes = src_nodes_in ? src_nodes_in : g_nodes;
    __shared__ __align__(16) float s_w1t[48 * HID];
    __shared__ __align__(16) float s_w2t[HID * F];
    __shared__ __align__(16) float s_ws[16 * HID];
    __shared__ __align__(16) float s_wr[16 * HID];
    __shared__ __align__(16) float s_b1[HID];
    __shared__ __align__(16) float s_b2[F];
    __shared__ __align__(16) float s_eb1[HID];
    for (int i = threadIdx.x; i < 48 * HID; i += blockDim.x) {
        int k = i >> 6, h = i & 63;
        s_w1t[i] = W1[h * 48 + k];
    }
    for (int i = threadIdx.x; i < HID * F; i += blockDim.x) {
        int h = i >> 4, o = i & 15;
        s_w2t[i] = W2[o * HID + h];
    }
    for (int i = threadIdx.x; i < 16 * HID; i += blockDim.x) {
        int k = i >> 6, h = i & 63;
        s_ws[i] = eW1[h * 48 + 16 + k];
        s_wr[i] = eW1[h * 48 + 32 + k];
    }
    if (threadIdx.x < HID) { s_b1[threadIdx.x] = b1[threadIdx.x]; s_eb1[threadIdx.x] = eb1[threadIdx.x]; }
    if (threadIdx.x < F)   s_b2[threadIdx.x] = b2[threadIdx.x];
    __syncthreads();

    int n = blockIdx.x * blockDim.x + threadIdx.x;
    if (n >= NN) return;

    ull acc[HID / 2];
#pragma unroll
    for (int j = 0; j < HID / 4; j++) {
        ulonglong2 bv = *reinterpret_cast<const ulonglong2*>(&s_b1[j * 4]);
        acc[2 * j] = bv.x; acc[2 * j + 1] = bv.y;
    }
#pragma unroll
    for (int k = 0; k < 16; k++) {
        float xk = src_nodes[(size_t)k * NN + n];
        ull xs = pack2(xk, xk);
        const ulonglong2* w = reinterpret_cast<const ulonglong2*>(&s_w1t[k * HID]);
#pragma unroll
        for (int m = 0; m < 16; m++) {
            ulonglong2 wv = w[m];
            acc[2 * m]     = fma2(wv.x, xs, acc[2 * m]);
            acc[2 * m + 1] = fma2(wv.y, xs, acc[2 * m + 1]);
        }
    }
#pragma unroll
    for (int seg = 0; seg < 2; seg++) {
        const float* aggr = seg == 0 ? &g_sent[(size_t)n * F] : &g_recv[(size_t)n * F];
        float xv[16];
#pragma unroll
        for (int q = 0; q < 4; q++) {
            float4 v = *reinterpret_cast<const float4*>(&aggr[q * 4]);
            xv[q * 4] = v.x; xv[q * 4 + 1] = v.y; xv[q * 4 + 2] = v.z; xv[q * 4 + 3] = v.w;
        }
#pragma unroll
        for (int k = 0; k < 16; k++) {
            ull xs = pack2(xv[k], xv[k]);
            const ulonglong2* w = reinterpret_cast<const ulonglong2*>(&s_w1t[((seg + 1) * 16 + k) * HID]);
#pragma unroll
            for (int m = 0; m < 16; m++) {
                ulonglong2 wv = w[m];
                acc[2 * m]     = fma2(wv.x, xs, acc[2 * m]);
                acc[2 * m + 1] = fma2(wv.y, xs, acc[2 * m + 1]);
            }
        }
    }

    ull o[F / 2];
#pragma unroll
    for (int j = 0; j < 4; j++) {
        ulonglong2 bv = *reinterpret_cast<const ulonglong2*>(&s_b2[j * 4]);
        o[2 * j] = bv.x; o[2 * j + 1] = bv.y;
    }
#pragma unroll
    for (int h = 0; h < HID; h += 2) {
        float h0, h1; unpack2(acc[h >> 1], h0, h1);
        h0 = fmaxf(h0, 0.f); h1 = fmaxf(h1, 0.f);
        ull x0 = pack2(h0, h0), x1 = pack2(h1, h1);
        const ulonglong2* w0 = reinterpret_cast<const ulonglong2*>(&s_w2t[h * F]);
        const ulonglong2* w1 = reinterpret_cast<const ulonglong2*>(&s_w2t[(h + 1) * F]);
#pragma unroll
        for (int m = 0; m < 4; m++) {
            ulonglong2 a = w0[m], b = w1[m];
            o[2 * m]     = fma2(a.x, x0, o[2 * m]);
            o[2 * m]     = fma2(b.x, x1, o[2 * m]);
            o[2 * m + 1] = fma2(a.y, x0, o[2 * m + 1]);
            o[2 * m + 1] = fma2(b.y, x1, o[2 * m + 1]);
        }
    }
    float y[F];
#pragma unroll
    for (int j = 0; j < F / 2; j++) unpack2(o[j], y[2 * j], y[2 * j + 1]);
#pragma unroll
    for (int k = 0; k < F; k++) {
        g_nodes[(size_t)k * NN + n] = y[k];
    }
    if (out_nodes) {
#pragma unroll
        for (int k = 0; k < F; k++) out_nodes[(size_t)k * NN + n] = y[k];
    }

#pragma unroll
    for (int j = 0; j < HID / 4; j++) {
        ulonglong2 bv = *reinterpret_cast<const ulonglong2*>(&s_eb1[j * 4]);
        acc[2 * j] = bv.x; acc[2 * j + 1] = bv.y;
    }
#pragma unroll
    for (int k = 0; k < 16; k++) {
        ull xs = pack2(y[k], y[k]);
        const ulonglong2* w = reinterpret_cast<const ulonglong2*>(&s_ws[k * HID]);
#pragma unroll
        for (int m = 0; m < 16; m++) {
            ulonglong2 wv = w[m];
            acc[2 * m]     = fma2(wv.x, xs, acc[2 * m]);
            acc[2 * m + 1] = fma2(wv.y, xs, acc[2 * m + 1]);
        }
    }
    ull* outp = reinterpret_cast<ull*>(&g_ps[(size_t)n * HID]);
#pragma unroll
    for (int j = 0; j < HID / 2; j++) outp[j] = acc[j];

#pragma unroll
    for (int j = 0; j < HID / 2; j++) acc[j] = 0ull;
#pragma unroll
    for (int k = 0; k < 16; k++) {
        ull xs = pack2(y[k], y[k]);
        const ulonglong2* w = reinterpret_cast<const ulonglong2*>(&s_wr[k * HID]);
#pragma unroll
        for (int m = 0; m < 16; m++) {
            ulonglong2 wv = w[m];
            acc[2 * m]     = fma2(wv.x, xs, acc[2 * m]);
            acc[2 * m + 1] = fma2(wv.y, xs, acc[2 * m + 1]);
        }
    }
    outp = reinterpret_cast<ull*>(&g_pr[(size_t)n * HID]);
#pragma unroll
    for (int j = 0; j < HID / 2; j++) outp[j] = acc[j];
}

// ---------------- edge MLP: R2 structure + [E][F] layout + prefetch ----------
#define ETPB 256
#define SG_STRIDE 68
#define EDGE_SMEM_FLOATS (ETPB * SG_STRIDE + 16 * 64 + 64 * 16 + 16)

__global__ void __launch_bounds__(ETPB, 2)
edge_mlp_kernel(const float* src_fe, float* dst_fe,
                const int* __restrict__ snd, const int* __restrict__ rcv,
                const float* __restrict__ eW1, const float* __restrict__ eW2,
                const float* __restrict__ eb2, int do_scatter) {
    extern __shared__ __align__(16) float smem[];
    float* s_g   = smem;                         // ETPB x 68
    float* s_w1t = smem + ETPB * SG_STRIDE;      // [k][h]  16x64
    float* s_w2t = s_w1t + 16 * 64;              // [h][o]  64x16
    float* s_b2  = s_w2t + 64 * 16;              // 16

    const int tid = threadIdx.x;
    const int e0 = blockIdx.x * ETPB;
    const size_t e = (size_t)e0 + tid;

    // ---- PREFETCH: edge features + own indices (overlaps staging + barrier)
    float x[16];
    if (src_fe) {
        // round 0: [F][E] strided input
#pragma unroll
        for (int k = 0; k < 16; k++) x[k] = __ldcs(&src_fe[(size_t)k * EE + e]);
    } else {
        // internal [E][F]: 4 x LDG.128
#pragma unroll
        for (int q = 0; q < 4; q++) {
            float4 v = __ldcs(reinterpret_cast<const float4*>(&g_edges[e * F + q * 4]));
            x[q * 4] = v.x; x[q * 4 + 1] = v.y; x[q * 4 + 2] = v.z; x[q * 4 + 3] = v.w;
        }
    }
    const int s_me = snd[e];
    const int r_me = rcv[e];

    for (int i = tid; i < 16 * 64; i += ETPB) { int k = i >> 6, h = i & 63; s_w1t[i] = eW1[h * 48 + k]; }
    for (int i = tid; i < 64 * 16; i += ETPB) { int h = i >> 4, o = i & 15; s_w2t[i] = eW2[o * 64 + h]; }
    if (tid < 16) s_b2[tid] = eb2[tid];

    // ---- cooperative gather staging: s_g[el][:] = g_ps[s_el][:] + g_pr[r_el][:]
    {
        const int wid  = tid >> 5;
        const int lane = tid & 31;
        const int sub  = lane >> 4;
        const int c    = lane & 15;
#pragma unroll
        for (int i = 0; i < 32; i += 2) {
            int el = wid * 32 + i + sub;
            int s = snd[e0 + el];
            int r = rcv[e0 + el];
            ulonglong2 a = *reinterpret_cast<const ulonglong2*>(&g_ps[(size_t)s * HID + c * 4]);
            ulonglong2 b = *reinterpret_cast<const ulonglong2*>(&g_pr[(size_t)r * HID + c * 4]);
            ulonglong2 v; v.x = add2(a.x, b.x); v.y = add2(a.y, b.y);
            *reinterpret_cast<ulonglong2*>(&s_g[el * SG_STRIDE + c * 4]) = v;
        }
    }
    __syncthreads();

    // ---- layer-1 accumulators from staged gather (eb1 folded into g_ps)
    ull acc[HID / 2];
    {
        const float* grow = &s_g[tid * SG_STRIDE];
#pragma unroll
        for (int m = 0; m < 16; m++) {
            ulonglong2 v = *reinterpret_cast<const ulonglong2*>(&grow[m * 4]);
            acc[2 * m] = v.x; acc[2 * m + 1] = v.y;
        }
    }

    // ---- layer 1: += eW1_e @ x (x already in registers)
#pragma unroll
    for (int k = 0; k < 16; k++) {
        ull xs = pack2(x[k], x[k]);
        const ulonglong2* w = reinterpret_cast<const ulonglong2*>(&s_w1t[k * HID]);
#pragma unroll
        for (int m = 0; m < 16; m++) {
            ulonglong2 wv = w[m];
            acc[2 * m]     = fma2(wv.x, xs, acc[2 * m]);
            acc[2 * m + 1] = fma2(wv.y, xs, acc[2 * m + 1]);
        }
    }

    // ---- layer 2: relu -> 16 outputs
    ull o[F / 2];
#pragma unroll
    for (int j = 0; j < 4; j++) {
        ulonglong2 bv = *reinterpret_cast<const ulonglong2*>(&s_b2[j * 4]);
        o[2 * j] = bv.x; o[2 * j + 1] = bv.y;
    }
#pragma unroll
    for (int h = 0; h < HID; h += 2) {
        float h0, h1; unpack2(acc[h >> 1], h0, h1);
        h0 = fmaxf(h0, 0.f); h1 = fmaxf(h1, 0.f);
        ull x0 = pack2(h0, h0), x1 = pack2(h1, h1);
        const ulonglong2* w0 = reinterpret_cast<const ulonglong2*>(&s_w2t[h * F]);
        const ulonglong2* w1 = reinterpret_cast<const ulonglong2*>(&s_w2t[(h + 1) * F]);
#pragma unroll
        for (int m = 0; m < 4; m++) {
            ulonglong2 a = w0[m], b = w1[m];
            o[2 * m]     = fma2(a.x, x0, o[2 * m]);
            o[2 * m]     = fma2(b.x, x1, o[2 * m]);
            o[2 * m + 1] = fma2(a.y, x0, o[2 * m + 1]);
            o[2 * m + 1] = fma2(b.y, x1, o[2 * m + 1]);
        }
    }

    float ov[F];
#pragma unroll
    for (int j = 0; j < F / 2; j++) unpack2(o[j], ov[2 * j], ov[2 * j + 1]);

    // ---- write new edge features
    if (dst_fe) {
        // final round: [F][E] strided output
#pragma unroll
        for (int f = 0; f < F; f++) __stcs(&dst_fe[(size_t)f * EE + e], ov[f]);
    } else {
        // internal [E][F]: 4 x STG.128
#pragma unroll
        for (int q = 0; q < 4; q++) {
            float4 v = make_float4(ov[q * 4], ov[q * 4 + 1], ov[q * 4 + 2], ov[q * 4 + 3]);
            __stcs(reinterpret_cast<float4*>(&g_edges[e * F + q * 4]), v);
        }
    }

    // ---- fused scatter into next round's aggregates
    if (do_scatter) {
        float* ps = &g_sent[(size_t)s_me * F];
        float* pr = &g_recv[(size_t)r_me * F];
#pragma unroll
        for (int f = 0; f < F; f += 4) {
            asm volatile("red.global.add.v4.f32 [%0], {%1,%2,%3,%4};"
                         :: "l"(ps + f), "f"(ov[f]), "f"(ov[f + 1]), "f"(ov[f + 2]), "f"(ov[f + 3])
                         : "memory");
            asm volatile("red.global.add.v4.f32 [%0], {%1,%2,%3,%4};"
                         :: "l"(pr + f), "f"(ov[f]), "f"(ov[f + 1]), "f"(ov[f + 2]), "f"(ov[f + 3])
                         : "memory");
        }
    }
}

extern "C" void kernel_launch(void* const* d_in, const int* in_sizes, int n_in,
                              void* d_out, int out_size) {
    const float* nodes     = (const float*)d_in[0];
    const float* edges     = (const float*)d_in[1];
    const int*   receivers = (const int*)  d_in[2];
    const int*   senders   = (const int*)  d_in[3];
    const float* nW1 = (const float*)d_in[4];
    const float* nb1 = (const float*)d_in[5];
    const float* nW2 = (const float*)d_in[6];
    const float* nb2 = (const float*)d_in[7];
    const float* eW1 = (const float*)d_in[8];
    const float* eb1 = (const float*)d_in[9];
    const float* eW2 = (const float*)d_in[10];
    const float* eb2 = (const float*)d_in[11];
    float* out_nodes = (float*)d_out;
    float* out_edges = (float*)d_out + (size_t)F * NN;

    const int EDGE_BLOCKS = EE / ETPB;                 // 12500
    const int NODE_BLOCKS = (NN + 255) / 256;          // 391
    const int ZERO_BLOCKS = ((NN * F) / 4 + 255) / 256;
    const int EDGE_SMEM = EDGE_SMEM_FLOATS * 4;        // 77888 bytes

    static int configured = 0;
    if (!configured) {
        cudaFuncSetAttribute(edge_mlp_kernel, cudaFuncAttributeMaxDynamicSharedMemorySize, EDGE_SMEM);
        configured = 1;
    }

    zero_agg_kernel<<<ZERO_BLOCKS, 256>>>();
    scatter_kernel<<<(EE + 255) / 256, 256>>>(edges, senders, receivers);

    for (int round = 0; round < ROUNDS; round++) {
        node_proj_kernel<<<NODE_BLOCKS, 256>>>(
            (round == 0) ? nodes : (const float*)0,
            (round == ROUNDS - 1) ? out_nodes : (float*)0,
            nW1, nb1, nW2, nb2, eW1, eb1);
        int do_scatter = (round < ROUNDS - 1);
        if (do_scatter) zero_agg_kernel<<<ZERO_BLOCKS, 256>>>();
        edge_mlp_kernel<<<EDGE_BLOCKS, ETPB, EDGE_SMEM>>>(
            (round == 0) ? edges : (const float*)0,
            (round == ROUNDS - 1) ? out_edges : (float*)0,
            senders, receivers, eW1, eW2, eb2, do_scatter);
    }
}